// round 11
// baseline (speedup 1.0000x reference)
#include <cuda_runtime.h>

#define C    256
#define CH   128
#define HWn  262144
#define HW4  65536
#define SEGS 16
#define SEG_F4 4096   // HW4 / SEGS
#define EPS  1e-5f

// k3 tiling: 16 pixels per tile, double-buffered, 6 CTAs/SM
#define TP     16
#define TP4    4
#define TILE_F  (C * TP)       // 4096 floats = 16 KB
#define NTILES  (HWn / TP)     // 16384 tiles

__device__ float d_partials[C * SEGS];
__device__ float d_g[C];
__device__ float d_v[C];
__device__ float d_b0;

// ---------------- Kernel 1: per-channel spatial sums ------------------------------
__global__ void k1_sums(const float4* __restrict__ x4) {
    const int c = blockIdx.y, seg = blockIdx.x, t = threadIdx.x;
    const float4* xc = x4 + (size_t)c * HW4 + (size_t)seg * SEG_F4;
    float s = 0.f;
#pragma unroll
    for (int j = 0; j < 16; j++) {
        float4 u = xc[t + j * 256];
        s += (u.x + u.y) + (u.z + u.w);
    }
    __shared__ float red[256];
    red[t] = s;
    __syncthreads();
    for (int off = 128; off > 0; off >>= 1) {
        if (t < off) red[t] += red[t + off];
        __syncthreads();
    }
    if (t == 0) d_partials[c * SEGS + seg] = red[0];
}

// ---------------- Kernel 2: all the tiny algebra (1 block) ------------------------
__global__ void k2_scalars(const float* __restrict__ cv1w, const float* __restrict__ cv1b,
                           const float* __restrict__ cv3w, const float* __restrict__ cv3b,
                           const float* __restrict__ lng,  const float* __restrict__ lnb,
                           const float* __restrict__ sp1w, const float* __restrict__ sp1b,
                           const float* __restrict__ sp2w, const float* __restrict__ sp2b) {
    __shared__ float S[C];
    __shared__ float ybuf[CH];
    __shared__ float s2[CH];
    __shared__ float wsm[CH];
    __shared__ float red[256];
    const int t = threadIdx.x;

    {
        float s = 0.f;
#pragma unroll
        for (int j = 0; j < SEGS; j++) s += d_partials[t * SEGS + j];
        S[t] = s;
    }
    __syncthreads();

    if (t < CH) {
        float a = 0.f;
        for (int c = 0; c < C; c++) a += cv1w[t * C + c] * S[c];
        ybuf[t] = a + (float)HWn * cv1b[t];
    } else {
        const int u = t - CH;
        float a = 0.f;
        for (int c = 0; c < C; c++) a += sp2w[u * C + c] * S[c];
        s2[u] = a * (1.f / (float)HWn) + sp2b[u];
    }
    __syncthreads();

    float zv = cv3b[t];
    for (int c = 0; c < CH; c++) zv += cv3w[t * CH + c] * ybuf[c];

    red[t] = zv;
    __syncthreads();
    for (int off = 128; off > 0; off >>= 1) {
        if (t < off) red[t] += red[t + off];
        __syncthreads();
    }
    const float mu = red[0] * (1.f / (float)C);
    __syncthreads();
    red[t] = zv * zv;
    __syncthreads();
    for (int off = 128; off > 0; off >>= 1) {
        if (t < off) red[t] += red[t + off];
        __syncthreads();
    }
    const float var = red[0] * (1.f / (float)C) - mu * mu;
    __syncthreads();

    const float zn = (zv - mu) * rsqrtf(var + EPS) * lng[t] + lnb[t];
    d_g[t] = 1.f / (1.f + expf(-zn));

    red[t] = (t < CH) ? s2[t] : -1e30f;
    __syncthreads();
    for (int off = 128; off > 0; off >>= 1) {
        if (t < off) red[t] = fmaxf(red[t], red[t + off]);
        __syncthreads();
    }
    const float mx = red[0];
    __syncthreads();
    red[t] = (t < CH) ? expf(s2[t] - mx) : 0.f;
    __syncthreads();
    for (int off = 128; off > 0; off >>= 1) {
        if (t < off) red[t] += red[t + off];
        __syncthreads();
    }
    const float denom = red[0];
    __syncthreads();
    if (t < CH) wsm[t] = expf(s2[t] - mx) / denom;
    __syncthreads();

    {
        float vv = 0.f;
        for (int c_ = 0; c_ < CH; c_++) vv += wsm[c_] * sp1w[c_ * C + t];
        d_v[t] = vv;
    }
    if (t == 0) {
        float b0 = 0.f;
        for (int c_ = 0; c_ < CH; c_++) b0 += wsm[c_] * sp1b[c_];
        d_b0 = b0;
    }
}

// ---------------- Kernel 3: pipelined fused yb + output (16-px tiles, 6 CTA/SM) ---
__device__ __forceinline__ void k3_prefetch(const float4* __restrict__ x4,
                                            float* buf, int tile, int t) {
    if (tile < NTILES) {
        unsigned dst_base = (unsigned)__cvta_generic_to_shared(buf);
        const int base4 = tile * TP4;
#pragma unroll
        for (int j = 0; j < 4; j++) {
            int i4 = t + j * 256;
            int c = i4 >> 2, p4 = i4 & 3;
            const float4* src = x4 + (size_t)c * HW4 + base4 + p4;
            unsigned dst = dst_base + i4 * 16;
            asm volatile("cp.async.cg.shared.global [%0], [%1], 16;\n" :: "r"(dst), "l"(src));
        }
    }
    asm volatile("cp.async.commit_group;\n");   // empty group OK when out of range
}

__global__ __launch_bounds__(256, 6)
void k3_out(const float4* __restrict__ x4, float4* __restrict__ out4, int gs) {
    extern __shared__ float sm[];
    float* buf0 = sm;                    // TILE_F
    float* buf1 = sm + TILE_F;           // TILE_F
    float* sv   = sm + 2 * TILE_F;       // C
    float* sg   = sv + C;                // C
    float* part = sg + C;                // 256
    float* sy   = part + 256;            // TP

    const int t = threadIdx.x;
    sv[t] = d_v[t];
    sg[t] = d_g[t];
    const float b0 = d_b0;

    int tile = blockIdx.x;
    if (tile >= NTILES) return;
    k3_prefetch(x4, buf0, tile, t);
    k3_prefetch(x4, buf1, tile + gs, t);

    int i = 0;
    for (; tile < NTILES; tile += gs, i++) {
        float* cur = (i & 1) ? buf1 : buf0;
        float4* cur4 = (float4*)cur;

        asm volatile("cp.async.wait_group 1;\n");   // this tile's group landed
        __syncthreads();

        // yb partial dots: p = pixel (0..15), q = channel 16-group (0..15)
        {
            const int p = t & 15, q = t >> 4;
            float acc = 0.f;
            const float* tp_ = cur + (q * 16) * TP + p;
            const float* vp  = sv + q * 16;
#pragma unroll
            for (int c = 0; c < 16; c++) acc += vp[c] * tp_[c * TP];
            part[q * TP + p] = acc;
        }
        __syncthreads();
        if (t < TP) {
            float yb = b0;
#pragma unroll
            for (int q = 0; q < 16; q++) yb += part[q * TP + t];
            sy[t] = 1.f / (1.f + expf(-yb));
        }
        __syncthreads();

        // out = (g[c] + sigmoid(yb[p])) * x
        const int base4 = tile * TP4;
#pragma unroll
        for (int j = 0; j < 4; j++) {
            int i4 = t + j * 256;
            int c = i4 >> 2, p4 = i4 & 3;
            float4 xv = cur4[i4];
            const float gv = sg[c];
            const int p = p4 * 4;
            float4 o;
            o.x = (gv + sy[p + 0]) * xv.x;
            o.y = (gv + sy[p + 1]) * xv.y;
            o.z = (gv + sy[p + 2]) * xv.z;
            o.w = (gv + sy[p + 3]) * xv.w;
            out4[(size_t)c * HW4 + base4 + p4] = o;
        }
        __syncthreads();                         // cur consumed
        k3_prefetch(x4, cur, tile + 2 * gs, t);  // refill cur for tile i+2
    }
}

// ---------------- Launch ----------------------------------------------------------
extern "C" void kernel_launch(void* const* d_in, const int* in_sizes, int n_in,
                              void* d_out, int out_size) {
    const float* x    = (const float*)d_in[0];
    const float* cv1w = (const float*)d_in[1];
    const float* cv1b = (const float*)d_in[2];
    // d_in[3], d_in[4] = ch_cv2_w/b : mathematically unused (softmax over size-1 dim)
    const float* cv3w = (const float*)d_in[5];
    const float* cv3b = (const float*)d_in[6];
    const float* lng  = (const float*)d_in[7];
    const float* lnb  = (const float*)d_in[8];
    const float* sp1w = (const float*)d_in[9];
    const float* sp1b = (const float*)d_in[10];
    const float* sp2w = (const float*)d_in[11];
    const float* sp2b = (const float*)d_in[12];

    int nsm = 148;
    cudaDeviceGetAttribute(&nsm, cudaDevAttrMultiProcessorCount, 0);
    const int grid3 = nsm * 6;   // 6 CTAs/SM @ ~35.9 KB smem each -> 48 warps/SM

    dim3 g1(SEGS, C);
    k1_sums<<<g1, 256>>>((const float4*)x);
    k2_scalars<<<1, 256>>>(cv1w, cv1b, cv3w, cv3b, lng, lnb, sp1w, sp1b, sp2w, sp2b);

    const int smem_bytes = (2 * TILE_F + C + C + 256 + TP) * (int)sizeof(float);
    cudaFuncSetAttribute(k3_out, cudaFuncAttributeMaxDynamicSharedMemorySize, smem_bytes);
    k3_out<<<grid3, 256, smem_bytes>>>((const float4*)x, (float4*)d_out, grid3);
}

// round 12
// speedup vs baseline: 1.2748x; 1.2748x over previous
#include <cuda_runtime.h>

#define C    256
#define CH   128
#define HWn  262144
#define HW4  65536
#define SEGS 16
#define SEG_F4 4096   // HW4 / SEGS
#define EPS  1e-5f

// k3 tiling: 32 pixels per tile, depth-2 cp.async pipeline, 3 CTAs/SM, work-stealing
#define TP     32
#define TP4    8
#define TILE_F  (C * TP)       // 8192 floats = 32 KB
#define NTILES  (HWn / TP)     // 8192 tiles

__device__ float d_partials[C * SEGS];
__device__ float d_g[C];
__device__ float d_v[C];
__device__ float d_b0;
__device__ unsigned d_k1done;   // zero at load; reset by last k1 CTA each call
__device__ int d_tilectr;       // reset by last k1 CTA each call

// ---------------- Kernel 1: channel sums + (last CTA) all the tiny algebra --------
__global__ void k1_sums(const float4* __restrict__ x4,
                        const float* __restrict__ cv1w, const float* __restrict__ cv1b,
                        const float* __restrict__ cv3w, const float* __restrict__ cv3b,
                        const float* __restrict__ lng,  const float* __restrict__ lnb,
                        const float* __restrict__ sp1w, const float* __restrict__ sp1b,
                        const float* __restrict__ sp2w, const float* __restrict__ sp2b) {
    const int c = blockIdx.y, seg = blockIdx.x, t = threadIdx.x;
    const float4* xc = x4 + (size_t)c * HW4 + (size_t)seg * SEG_F4;
    float s = 0.f;
#pragma unroll
    for (int j = 0; j < 16; j++) {
        float4 u = xc[t + j * 256];
        s += (u.x + u.y) + (u.z + u.w);
    }
    __shared__ float red[256];
    red[t] = s;
    __syncthreads();
    for (int off = 128; off > 0; off >>= 1) {
        if (t < off) red[t] += red[t + off];
        __syncthreads();
    }
    if (t == 0) d_partials[c * SEGS + seg] = red[0];

    // ---- last-CTA detection ----
    __shared__ unsigned slast;
    if (t == 0) {
        __threadfence();
        unsigned old = atomicAdd(&d_k1done, 1u);
        slast = (old == (unsigned)(SEGS * C - 1)) ? 1u : 0u;
        if (slast) __threadfence();
    }
    __syncthreads();
    if (!slast) return;

    // ---- scalar algebra (exactly the former k2, this CTA only) ----
    if (t == 0) { d_k1done = 0u; d_tilectr = 0; }   // reset for next replay / k3

    __shared__ float S[C];
    __shared__ float l1[C];     // ybuf in [0,CH), s2pre/wsm in [CH,2CH)
    {
        float ss = 0.f;
#pragma unroll
        for (int j = 0; j < SEGS; j++) ss += d_partials[t * SEGS + j];
        S[t] = ss;
    }
    __syncthreads();

    if (t < CH) {
        float a = 0.f;
        for (int cc = 0; cc < C; cc++) a += cv1w[t * C + cc] * S[cc];
        l1[t] = a + (float)HWn * cv1b[t];
    } else {
        const int u = t - CH;
        float a = 0.f;
        for (int cc = 0; cc < C; cc++) a += sp2w[u * C + cc] * S[cc];
        l1[t] = a * (1.f / (float)HWn) + sp2b[u];
    }
    __syncthreads();

    float zv = cv3b[t];
    for (int cc = 0; cc < CH; cc++) zv += cv3w[t * CH + cc] * l1[cc];

    red[t] = zv;
    __syncthreads();
    for (int off = 128; off > 0; off >>= 1) {
        if (t < off) red[t] += red[t + off];
        __syncthreads();
    }
    const float mu = red[0] * (1.f / (float)C);
    __syncthreads();
    red[t] = zv * zv;
    __syncthreads();
    for (int off = 128; off > 0; off >>= 1) {
        if (t < off) red[t] += red[t + off];
        __syncthreads();
    }
    const float var = red[0] * (1.f / (float)C) - mu * mu;
    __syncthreads();

    const float zn = (zv - mu) * rsqrtf(var + EPS) * lng[t] + lnb[t];
    d_g[t] = 1.f / (1.f + expf(-zn));

    red[t] = (t < CH) ? l1[CH + t] : -1e30f;
    __syncthreads();
    for (int off = 128; off > 0; off >>= 1) {
        if (t < off) red[t] = fmaxf(red[t], red[t + off]);
        __syncthreads();
    }
    const float mx = red[0];
    __syncthreads();
    red[t] = (t < CH) ? expf(l1[CH + t] - mx) : 0.f;
    __syncthreads();
    for (int off = 128; off > 0; off >>= 1) {
        if (t < off) red[t] += red[t + off];
        __syncthreads();
    }
    const float denom = red[0];
    __syncthreads();
    if (t < CH) l1[CH + t] = expf(l1[CH + t] - mx) / denom;   // wsm
    __syncthreads();

    {
        float vv = 0.f;
        for (int c_ = 0; c_ < CH; c_++) vv += l1[CH + c_] * sp1w[c_ * C + t];
        d_v[t] = vv;
    }
    if (t == 0) {
        float bb = 0.f;
        for (int c_ = 0; c_ < CH; c_++) bb += l1[CH + c_] * sp1b[c_];
        d_b0 = bb;
    }
}

// ---------------- Kernel 3: pipelined fused yb + output (work-stealing) -----------
__device__ __forceinline__ void k3_prefetch(const float4* __restrict__ x4,
                                            float* buf, int tile, int t) {
    if (tile < NTILES) {
        unsigned dst_base = (unsigned)__cvta_generic_to_shared(buf);
        const int base4 = tile * TP4;
#pragma unroll
        for (int j = 0; j < 8; j++) {
            int i4 = t + j * 256;
            int c = i4 >> 3, p4 = i4 & 7;
            const float4* src = x4 + (size_t)c * HW4 + base4 + p4;
            unsigned dst = dst_base + i4 * 16;
            asm volatile("cp.async.cg.shared.global [%0], [%1], 16;\n" :: "r"(dst), "l"(src));
        }
    }
    asm volatile("cp.async.commit_group;\n");   // empty group OK when out of range
}

__global__ __launch_bounds__(256, 3)
void k3_out(const float4* __restrict__ x4, float4* __restrict__ out4) {
    extern __shared__ float sm[];
    float* buf0 = sm;                    // TILE_F
    float* buf1 = sm + TILE_F;           // TILE_F
    float* sv   = sm + 2 * TILE_F;       // C
    float* sg   = sv + C;                // C
    float* part = sg + C;                // 256
    float* sy   = part + 256;            // TP
    __shared__ int ssteal[3];

    const int t = threadIdx.x;
    sv[t] = d_v[t];
    sg[t] = d_g[t];
    const float b0 = d_b0;

    if (t == 0) {
        ssteal[0] = atomicAdd(&d_tilectr, 1);
        ssteal[1] = atomicAdd(&d_tilectr, 1);
    }
    __syncthreads();
    int cur_t = ssteal[0], nxt_t = ssteal[1];
    k3_prefetch(x4, buf0, cur_t, t);
    k3_prefetch(x4, buf1, nxt_t, t);

    int i = 0;
    while (cur_t < NTILES) {
        float* cur = (i & 1) ? buf1 : buf0;
        float4* cur4 = (float4*)cur;

        if (t == 0) ssteal[2] = atomicAdd(&d_tilectr, 1);   // latency hidden by wait
        asm volatile("cp.async.wait_group 1;\n");           // current tile landed
        __syncthreads();                                    // publishes ssteal[2] too
        const int nn = ssteal[2];

        // yb partial dots: p = pixel (0..31), q = channel octant (0..7)
        {
            const int p = t & 31, q = t >> 5;
            float acc = 0.f;
            const float* tp_ = cur + (q * 32) * TP + p;
            const float* vp  = sv + q * 32;
#pragma unroll
            for (int c = 0; c < 32; c++) acc += vp[c] * tp_[c * TP];
            part[q * TP + p] = acc;
        }
        __syncthreads();
        if (t < TP) {
            float yb = b0;
#pragma unroll
            for (int q = 0; q < 8; q++) yb += part[q * TP + t];
            sy[t] = 1.f / (1.f + expf(-yb));
        }
        __syncthreads();

        // out = (g[c] + sigmoid(yb[p])) * x
        const int base4 = cur_t * TP4;
#pragma unroll
        for (int j = 0; j < 8; j++) {
            int i4 = t + j * 256;
            int c = i4 >> 3, p4 = i4 & 7;
            float4 xv = cur4[i4];
            const float gv = sg[c];
            const int p = p4 * 4;
            float4 o;
            o.x = (gv + sy[p + 0]) * xv.x;
            o.y = (gv + sy[p + 1]) * xv.y;
            o.z = (gv + sy[p + 2]) * xv.z;
            o.w = (gv + sy[p + 3]) * xv.w;
            out4[(size_t)c * HW4 + base4 + p4] = o;
        }
        __syncthreads();                 // cur consumed
        k3_prefetch(x4, cur, nn, t);     // refill cur with stolen tile
        cur_t = nxt_t;
        nxt_t = nn;
        i++;
    }
    asm volatile("cp.async.wait_group 0;\n");   // drain before exit
}

// ---------------- Launch ----------------------------------------------------------
extern "C" void kernel_launch(void* const* d_in, const int* in_sizes, int n_in,
                              void* d_out, int out_size) {
    const float* x    = (const float*)d_in[0];
    const float* cv1w = (const float*)d_in[1];
    const float* cv1b = (const float*)d_in[2];
    // d_in[3], d_in[4] = ch_cv2_w/b : mathematically unused (softmax over size-1 dim)
    const float* cv3w = (const float*)d_in[5];
    const float* cv3b = (const float*)d_in[6];
    const float* lng  = (const float*)d_in[7];
    const float* lnb  = (const float*)d_in[8];
    const float* sp1w = (const float*)d_in[9];
    const float* sp1b = (const float*)d_in[10];
    const float* sp2w = (const float*)d_in[11];
    const float* sp2b = (const float*)d_in[12];

    int nsm = 148;
    cudaDeviceGetAttribute(&nsm, cudaDevAttrMultiProcessorCount, 0);
    const int grid3 = nsm * 3;   // 3 CTAs/SM

    dim3 g1(SEGS, C);
    k1_sums<<<g1, 256>>>((const float4*)x, cv1w, cv1b, cv3w, cv3b, lng, lnb,
                         sp1w, sp1b, sp2w, sp2b);

    const int smem_bytes = (2 * TILE_F + C + C + 256 + TP) * (int)sizeof(float);
    cudaFuncSetAttribute(k3_out, cudaFuncAttributeMaxDynamicSharedMemorySize, smem_bytes);
    k3_out<<<grid3, 256, smem_bytes>>>((const float4*)x, (float4*)d_out);
}